// round 16
// baseline (speedup 1.0000x reference)
#include <cuda_runtime.h>
#include <cstdint>
#include <cstddef>

#define BB 4
#define NN 512
#define FF 16
#define EE 64
#define THREADS 128
#define ROWS_PER_CTA 2

#define LR_A 0.505f
#define LR_B 0.495f

typedef unsigned long long u64;
typedef unsigned int u32;

__device__ __forceinline__ u64 pk2(float lo, float hi) {
    u64 d; asm("mov.b64 %0, {%1, %2};" : "=l"(d) : "f"(lo), "f"(hi)); return d;
}
__device__ __forceinline__ void upk2(u64 v, float& lo, float& hi) {
    asm("mov.b64 {%0, %1}, %2;" : "=f"(lo), "=f"(hi) : "l"(v));
}
__device__ __forceinline__ u64 ffma2(u64 a, u64 b, u64 c) {
    u64 d; asm("fma.rn.f32x2 %0, %1, %2, %3;" : "=l"(d) : "l"(a), "l"(b), "l"(c)); return d;
}
__device__ __forceinline__ u64 fmul2(u64 a, u64 b) {
    u64 d; asm("mul.rn.f32x2 %0, %1, %2;" : "=l"(d) : "l"(a), "l"(b)); return d;
}
__device__ __forceinline__ unsigned smem_u32(const void* p) {
    unsigned r;
    asm("{ .reg .u64 t; cvta.to.shared.u64 t, %1; cvt.u32.u64 %0, t; }" : "=r"(r) : "l"(p));
    return r;
}
__device__ __forceinline__ void cp16(unsigned d, const void* s) {
    asm volatile("cp.async.cg.shared.global [%0], [%1], 16;" :: "r"(d), "l"(s));
}
__device__ __forceinline__ void cpcommit() { asm volatile("cp.async.commit_group;" ::: "memory"); }
template <int N> __device__ __forceinline__ void cpwait() {
    asm volatile("cp.async.wait_group %0;" :: "n"(N) : "memory");
}

// pack two f32 -> bf16x2 (first arg -> low half)
__device__ __forceinline__ u32 pk_bf16(float lo, float hi) {
    u32 d; asm("cvt.rn.bf16x2.f32 %0, %1, %2;" : "=r"(d) : "f"(hi), "f"(lo)); return d;
}
__device__ __forceinline__ float bf_lo(u32 p) { return __uint_as_float(p << 16); }
__device__ __forceinline__ float bf_hi(u32 p) { return __uint_as_float(p & 0xFFFF0000u); }

__device__ __forceinline__ void split2(float x0, float x1, u32& hi, u32& lo) {
    hi = pk_bf16(x0, x1);
    lo = pk_bf16(x0 - bf_lo(hi), x1 - bf_hi(hi));
}

// D(m16n8) += A(m16k16,bf16) * B(k16n8,bf16)
__device__ __forceinline__ void mma16(float d[4], const u32 a[4], const u32 b[2]) {
    asm volatile("mma.sync.aligned.m16n8k16.row.col.f32.bf16.bf16.f32 "
        "{%0,%1,%2,%3}, {%4,%5,%6,%7}, {%8,%9}, {%0,%1,%2,%3};"
        : "+f"(d[0]), "+f"(d[1]), "+f"(d[2]), "+f"(d[3])
        : "r"(a[0]), "r"(a[1]), "r"(a[2]), "r"(a[3]), "r"(b[0]), "r"(b[1]));
}

__global__ void __launch_bounds__(THREADS, 6)
edge_embed_bf16_kernel(const float* __restrict__ edge,
                       const float* __restrict__ adj,
                       const float* __restrict__ w4,
                       const float* __restrict__ w3,
                       float* __restrict__ out)
{
    // per-warp 8-deep ring of 8-j groups: each lane owns one 16B slot per buffer
    __shared__ float4 ring[4][8][32];          // 16 KB
    __shared__ float adj_s[ROWS_PER_CTA][NN];  // 4 KB
    __shared__ float Sp[4][EE];
    __shared__ float Sh[ROWS_PER_CTA][EE];

    const int tid  = threadIdx.x;
    const int lane = tid & 31;
    const int warp = tid >> 5;
    const int gid  = lane >> 2;      // 0..7  (B column within group)
    const int tig  = lane & 3;       // 0..3  (k chunk / D column pair)

    const int rloc = warp >> 1;                       // 0..1: row within CTA
    const int wh   = warp & 1;                        // half of the j range
    const int row  = blockIdx.x * ROWS_PER_CTA + rloc;

    const float* erow = edge + (size_t)row * (NN * FF);

    const int jbase = wh * 256;                       // this warp: 32 groups of 8 j
    const unsigned rbase = smem_u32(&ring[warp][0][lane]);   // +512B per buffer

    // ---- prologue: adj rows (into commit group 0) + 8 ring groups ----
    {
        // 2 rows x 512 floats = 256 float4, 2 per thread
        for (int idx = tid; idx < 256; idx += THREADS) {
            const int r = idx >> 7;
            const int c = (idx & 127) * 4;
            cp16(smem_u32(&adj_s[r][c]),
                 adj + (size_t)(blockIdx.x * ROWS_PER_CTA + r) * NN + c);
        }
        cp16(rbase, erow + (size_t)(jbase) * FF + lane * 4);
        cpcommit();
#pragma unroll
        for (int p = 1; p < 8; ++p) {
            cp16(rbase + p * 512, erow + (size_t)(jbase + p * 8) * FF + lane * 4);
            cpcommit();
        }
    }

    // ---- A = W4, 4 e-tiles pre-split in registers (k-permuted chunks) ----
    u32 Whi[4][4], Wlo[4][4];
#pragma unroll
    for (int et = 0; et < 4; ++et) {
        const int e0 = et * 16 + gid;
        float4 wa = __ldg(reinterpret_cast<const float4*>(w4 + e0 * FF) + tig);
        float4 wb = __ldg(reinterpret_cast<const float4*>(w4 + (e0 + 8) * FF) + tig);
        split2(wa.x, wa.y, Whi[et][0], Wlo[et][0]);
        split2(wb.x, wb.y, Whi[et][1], Wlo[et][1]);
        split2(wa.z, wa.w, Whi[et][2], Wlo[et][2]);
        split2(wb.z, wb.w, Whi[et][3], Wlo[et][3]);
    }

    u64 acc2[8];
#pragma unroll
    for (int i = 0; i < 8; ++i) acc2[i] = 0ULL;
    const u64 ABS2 = 0x7FFFFFFF7FFFFFFFULL;
    const u64 LRA2 = pk2(LR_A, LR_A);
    const u64 LRB2 = pk2(LR_B, LR_B);

    // group 0 + adj arrived for every warp; syncthreads makes adj visible CTA-wide
    cpwait<7>();
    __syncthreads();

    const float* arow_s = adj_s[rloc];

    // ---- main loop: 32 groups of 8 j per warp ----
#pragma unroll 8
    for (int gg = 0; gg < 32; ++gg) {
        const int jb = jbase + gg * 8;
        const int b  = gg & 7;

        cpwait<7>();                        // group gg guaranteed complete
        float4 c = ring[warp][b][lane];     // own slot: no sync needed

        // refill slot with group gg+8 (empty commit past the tail keeps invariant)
        if (gg + 8 < 32)
            cp16(rbase + b * 512, erow + (size_t)(jb + 64) * FF + lane * 4);
        cpcommit();

        // B fragments (hi/lo split)
        u32 bh[2], bl[2];
        split2(c.x, c.y, bh[0], bl[0]);     // k 2t..2t+1
        split2(c.z, c.w, bh[1], bl[1]);     // k 2t+8..2t+9

        // adj pair for this thread's two D columns (j = jb+2t, jb+2t+1)
        float2 aj = *reinterpret_cast<const float2*>(&arow_s[jb + 2 * tig]);
        const u64 a01 = pk2(aj.x, aj.y);
        const u64 aA2 = fmul2(a01, LRA2);
        const u64 aB2 = fmul2(a01, LRB2);

#pragma unroll
        for (int et = 0; et < 4; ++et) {
            float d[4] = {0.f, 0.f, 0.f, 0.f};
            mma16(d, Whi[et], bh);          // hi * hi
            mma16(d, Wlo[et], bh);          // lo * hi
            mma16(d, Whi[et], bl);          // hi * lo
            u64 v01 = pk2(d[0], d[1]);
            u64 v23 = pk2(d[2], d[3]);
            acc2[et * 2]     = ffma2(aA2, v01,        acc2[et * 2]);
            acc2[et * 2]     = ffma2(aB2, v01 & ABS2, acc2[et * 2]);
            acc2[et * 2 + 1] = ffma2(aA2, v23,        acc2[et * 2 + 1]);
            acc2[et * 2 + 1] = ffma2(aB2, v23 & ABS2, acc2[et * 2 + 1]);
        }
    }

    // ---- reduce: j-parity halves, then over tig (quad) ----
    float accf[8];
#pragma unroll
    for (int i = 0; i < 8; ++i) {
        float lo, hi; upk2(acc2[i], lo, hi);
        accf[i] = lo + hi;
    }
#pragma unroll
    for (int off = 1; off <= 2; off <<= 1) {
#pragma unroll
        for (int i = 0; i < 8; ++i)
            accf[i] += __shfl_xor_sync(0xFFFFFFFFu, accf[i], off);
    }
    if (tig == 0) {
#pragma unroll
        for (int et = 0; et < 4; ++et) {
            Sp[warp][et * 16 + gid]     = accf[et * 2];
            Sp[warp][et * 16 + gid + 8] = accf[et * 2 + 1];
        }
    }
    __syncthreads();

    // combine the two warps of each row
    if (tid < ROWS_PER_CTA * EE) {
        const int r = tid >> 6;
        const int e = tid & 63;
        Sh[r][e] = Sp[2 * r][e] + Sp[2 * r + 1][e];
    }
    __syncthreads();

    // ---- theta3: one output element per thread (2 rows x 64) ----
    if (tid < ROWS_PER_CTA * EE) {
        const int r = tid >> 6;
        const int o = tid & 63;
        const float* S = Sh[r];
        const float4* w3v = reinterpret_cast<const float4*>(w3 + o * EE);
        float acc = 0.0f;
#pragma unroll
        for (int k = 0; k < 16; ++k) {
            float4 w = __ldg(w3v + k);
            acc = fmaf(w.x, S[4 * k + 0], acc);
            acc = fmaf(w.y, S[4 * k + 1], acc);
            acc = fmaf(w.z, S[4 * k + 2], acc);
            acc = fmaf(w.w, S[4 * k + 3], acc);
        }
        out[(size_t)(blockIdx.x * ROWS_PER_CTA + r) * EE + o] = acc;
    }
}

extern "C" void kernel_launch(void* const* d_in, const int* in_sizes, int n_in,
                              void* d_out, int out_size) {
    const float* edge = (const float*)d_in[0];   // (4,512,512,16) f32
    const float* adj  = (const float*)d_in[1];   // (4,512,512)    f32
    const float* w4   = (const float*)d_in[2];   // (64,16)        f32
    const float* w3   = (const float*)d_in[3];   // (64,64)        f32
    float* out = (float*)d_out;                  // (4,512,64)     f32

    edge_embed_bf16_kernel<<<(BB * NN) / ROWS_PER_CTA, THREADS>>>(edge, adj, w4, w3, out);
}